// round 2
// baseline (speedup 1.0000x reference)
#include <cuda_runtime.h>
#include <cstdint>
#include <cstddef>

static constexpr int MDIM = 8192;   // 4*2048 tokens
static constexpr int KDIM = 4096;
static constexpr int NDIM = 4096;

// ---------------- scratch (alloc-free: __device__ globals) ----------------
__device__ __align__(1024) int8_t g_Aq[(size_t)MDIM * KDIM]; // Xq - 128 (s8)
__device__ __align__(1024) int8_t g_Wq[(size_t)NDIM * KDIM]; // Wq (s8)
__device__ float g_sa[MDIM];   // activation scale per token
__device__ float g_czp[MDIM];  // 128 - zp  per token
__device__ float g_sw[NDIM];   // weight scale per row
__device__ float g_rs[NDIM];   // rowsum of Wq per row (as float, exact int)

// ---------------- PTX helpers ----------------
__device__ __forceinline__ uint32_t smem_u32(const void* p) {
    uint32_t a;
    asm("{ .reg .u64 t; cvta.to.shared.u64 t, %1; cvt.u32.u64 %0, t; }" : "=r"(a) : "l"(p));
    return a;
}
#define CPA16(s, g) asm volatile("cp.async.cg.shared.global [%0], [%1], 16;" :: "r"(s), "l"(g))
#define CP_COMMIT()  asm volatile("cp.async.commit_group;" ::: "memory")
#define CP_WAIT(n)   asm volatile("cp.async.wait_group %0;" :: "n"(n) : "memory")
#define LDSM4(r0, r1, r2, r3, addr) \
    asm volatile("ldmatrix.sync.aligned.m8n8.x4.shared.b16 {%0,%1,%2,%3}, [%4];" \
                 : "=r"(r0), "=r"(r1), "=r"(r2), "=r"(r3) : "r"(addr))
#define IMMA(c, a, b) \
    asm volatile("mma.sync.aligned.m16n8k32.row.col.s32.s8.s8.s32 " \
                 "{%0,%1,%2,%3}, {%4,%5,%6,%7}, {%8,%9}, {%0,%1,%2,%3};" \
                 : "+r"((c)[0]), "+r"((c)[1]), "+r"((c)[2]), "+r"((c)[3]) \
                 : "r"((a)[0]), "r"((a)[1]), "r"((a)[2]), "r"((a)[3]), \
                   "r"((b)[0]), "r"((b)[1]))

// ---------------- quantization kernels ----------------
// Per-token asymmetric uint8; store (Xq - 128) as s8, plus s and (128 - zp).
__global__ void __launch_bounds__(256) quant_x_kernel(const float* __restrict__ x) {
    const int m = blockIdx.x;
    const int t = threadIdx.x;
    const float4* row = reinterpret_cast<const float4*>(x + (size_t)m * KDIM);
    float4 v[4];
    float mn = 3.4e38f, mx = -3.4e38f;
#pragma unroll
    for (int i = 0; i < 4; i++) {
        v[i] = row[t * 4 + i];   // contiguous 16 floats per thread
        mn = fminf(mn, fminf(fminf(v[i].x, v[i].y), fminf(v[i].z, v[i].w)));
        mx = fmaxf(mx, fmaxf(fmaxf(v[i].x, v[i].y), fmaxf(v[i].z, v[i].w)));
    }
#pragma unroll
    for (int o = 16; o > 0; o >>= 1) {
        mn = fminf(mn, __shfl_xor_sync(0xffffffffu, mn, o));
        mx = fmaxf(mx, __shfl_xor_sync(0xffffffffu, mx, o));
    }
    __shared__ float smn[8], smx[8];
    if ((t & 31) == 0) { smn[t >> 5] = mn; smx[t >> 5] = mx; }
    __syncthreads();
    mn = smn[0]; mx = smx[0];
#pragma unroll
    for (int i = 1; i < 8; i++) { mn = fminf(mn, smn[i]); mx = fmaxf(mx, smx[i]); }

    const float rng = mx - mn;
    const float s = (rng > 0.0f) ? __fdiv_rn(rng, 255.0f) : 1.0f;
    const float zp = rintf(__fdiv_rn(-mn, s));

    uint32_t pk[4];
#pragma unroll
    for (int i = 0; i < 4; i++) {
        int q0 = (int)(fminf(fmaxf(rintf(__fdiv_rn(v[i].x, s)) + zp, 0.0f), 255.0f)) - 128;
        int q1 = (int)(fminf(fmaxf(rintf(__fdiv_rn(v[i].y, s)) + zp, 0.0f), 255.0f)) - 128;
        int q2 = (int)(fminf(fmaxf(rintf(__fdiv_rn(v[i].z, s)) + zp, 0.0f), 255.0f)) - 128;
        int q3 = (int)(fminf(fmaxf(rintf(__fdiv_rn(v[i].w, s)) + zp, 0.0f), 255.0f)) - 128;
        pk[i] = (uint32_t)(q0 & 255) | ((uint32_t)(q1 & 255) << 8) |
                ((uint32_t)(q2 & 255) << 16) | ((uint32_t)(q3 & 255) << 24);
    }
    *reinterpret_cast<uint4*>(g_Aq + (size_t)m * KDIM + t * 16) =
        make_uint4(pk[0], pk[1], pk[2], pk[3]);
    if (t == 0) { g_sa[m] = s; g_czp[m] = 128.0f - zp; }
}

// Per-row symmetric int8 weights; store Wq s8, scale, and rowsum(Wq).
__global__ void __launch_bounds__(256) quant_w_kernel(const float* __restrict__ w) {
    const int n = blockIdx.x;
    const int t = threadIdx.x;
    const float4* row = reinterpret_cast<const float4*>(w + (size_t)n * KDIM);
    float4 v[4];
    float amax = 0.0f;
#pragma unroll
    for (int i = 0; i < 4; i++) {
        v[i] = row[t * 4 + i];
        amax = fmaxf(amax, fmaxf(fmaxf(fabsf(v[i].x), fabsf(v[i].y)),
                                 fmaxf(fabsf(v[i].z), fabsf(v[i].w))));
    }
#pragma unroll
    for (int o = 16; o > 0; o >>= 1)
        amax = fmaxf(amax, __shfl_xor_sync(0xffffffffu, amax, o));
    __shared__ float sm[8];
    __shared__ int ssum[8];
    if ((t & 31) == 0) sm[t >> 5] = amax;
    __syncthreads();
    amax = sm[0];
#pragma unroll
    for (int i = 1; i < 8; i++) amax = fmaxf(amax, sm[i]);

    const float s = (amax > 0.0f) ? __fdiv_rn(amax, 127.0f) : 1.0f;

    uint32_t pk[4];
    int rsum = 0;
#pragma unroll
    for (int i = 0; i < 4; i++) {
        int q0 = (int)fminf(fmaxf(rintf(__fdiv_rn(v[i].x, s)), -127.0f), 127.0f);
        int q1 = (int)fminf(fmaxf(rintf(__fdiv_rn(v[i].y, s)), -127.0f), 127.0f);
        int q2 = (int)fminf(fmaxf(rintf(__fdiv_rn(v[i].z, s)), -127.0f), 127.0f);
        int q3 = (int)fminf(fmaxf(rintf(__fdiv_rn(v[i].w, s)), -127.0f), 127.0f);
        rsum += q0 + q1 + q2 + q3;
        pk[i] = (uint32_t)(q0 & 255) | ((uint32_t)(q1 & 255) << 8) |
                ((uint32_t)(q2 & 255) << 16) | ((uint32_t)(q3 & 255) << 24);
    }
    *reinterpret_cast<uint4*>(g_Wq + (size_t)n * KDIM + t * 16) =
        make_uint4(pk[0], pk[1], pk[2], pk[3]);

#pragma unroll
    for (int o = 16; o > 0; o >>= 1)
        rsum += __shfl_xor_sync(0xffffffffu, rsum, o);
    if ((t & 31) == 0) ssum[t >> 5] = rsum;
    __syncthreads();
    if (t == 0) {
        int tot = 0;
#pragma unroll
        for (int i = 0; i < 8; i++) tot += ssum[i];
        g_sw[n] = s;
        g_rs[n] = (float)tot;
    }
}

// ---------------- GEMM: s8 IMMA mma.sync, 128x128x64, 4-stage cp.async ----------------
static constexpr int BM = 128, BN = 128, BK = 64;
static constexpr int STAGES = 4;
static constexpr int NCHUNK = KDIM / BK;                 // 64
static constexpr int STAGE_BYTES = BM * BK + BN * BK;    // 16384
static constexpr uint32_t GEMM_SMEM = STAGES * STAGE_BYTES;  // 65536

__global__ void __launch_bounds__(256, 2)
gemm_kernel(const float* __restrict__ bias, float* __restrict__ out) {
    extern __shared__ int8_t smem[];
    const uint32_t sbase = smem_u32(smem);
    const int tid = threadIdx.x;
    const int wid = tid >> 5;
    const int lane = tid & 31;
    const int bm = blockIdx.y * BM;
    const int bn = blockIdx.x * BN;

    // ---- global->shared (cp.async) setup: 16B units, XOR swizzle ----
    // unit layout: row has 4 x 16B units; phys_unit = unit ^ ((row>>1)&3)
    const int ar = tid >> 2;          // 0..63
    const int au = tid & 3;           // unit
    const int8_t* gA0 = g_Aq + (size_t)(bm + ar) * KDIM + au * 16;
    const int8_t* gA1 = gA0 + (size_t)64 * KDIM;
    const int8_t* gB0 = g_Wq + (size_t)(bn + ar) * KDIM + au * 16;
    const int8_t* gB1 = gB0 + (size_t)64 * KDIM;
    const uint32_t swz = (uint32_t)((au ^ ((ar >> 1) & 3)) << 4);
    const uint32_t sA0 = sbase + ar * 64 + swz;          // rows 0..63
    const uint32_t sA1 = sA0 + 64 * 64;                  // rows 64..127
    const uint32_t sB0 = sA0 + BM * BK;                  // B block after A
    const uint32_t sB1 = sB0 + 64 * 64;

    // ---- warp tiling: 2 (M) x 4 (N); warp tile 64x32 ----
    const int warp_m = (wid & 1) << 6;    // 0 / 64
    const int warp_n = (wid >> 1) << 5;   // 0/32/64/96
    const int lr = lane & 7;
    const int lsw = (lr >> 1) & 3;        // swizzle bits from row bits [2:1]
    // A ldmatrix: matrix i = lane>>3: (i&1) -> +8 rows, (i>>1) -> k-half unit
    const int am_lo = (lane >> 3) & 1;
    const int am_hi = lane >> 4;
    const uint32_t offA = (uint32_t)((warp_m + am_lo * 8 + lr) * 64 +
                                     ((am_hi ^ lsw) << 4));
    // B ldmatrix: matrix i: (i&1) -> k-half unit, (i>>1) -> +8 n-rows
    const int bg_lo = (lane >> 3) & 1;
    const int bg_hi = lane >> 4;
    const uint32_t offB = (uint32_t)(BM * BK + (warp_n + bg_hi * 8 + lr) * 64 +
                                     ((bg_lo ^ lsw) << 4));

    int acc[4][4][4];
#pragma unroll
    for (int i = 0; i < 4; i++)
#pragma unroll
        for (int j = 0; j < 4; j++)
#pragma unroll
            for (int r = 0; r < 4; r++) acc[i][j][r] = 0;

    auto issue_load = [&](int c, int st) {
        const size_t go = (size_t)c * BK;
        const uint32_t so = (uint32_t)st * STAGE_BYTES;
        CPA16(sA0 + so, gA0 + go);
        CPA16(sA1 + so, gA1 + go);
        CPA16(sB0 + so, gB0 + go);
        CPA16(sB1 + so, gB1 + go);
    };

#pragma unroll
    for (int c = 0; c < STAGES - 1; c++) { issue_load(c, c); CP_COMMIT(); }

    for (int c = 0; c < NCHUNK; c++) {
        CP_WAIT(STAGES - 2);
        __syncthreads();
        const int nc = c + STAGES - 1;
        if (nc < NCHUNK) issue_load(nc, nc & (STAGES - 1));
        CP_COMMIT();

        const uint32_t st = sbase + (uint32_t)(c & (STAGES - 1)) * STAGE_BYTES;
#pragma unroll
        for (int s = 0; s < 2; s++) {
            uint32_t a[4][4], b[4][2];
#pragma unroll
            for (int mt = 0; mt < 4; mt++) {
                const uint32_t ad = (st + offA + mt * 1024) ^ (uint32_t)(s << 5);
                LDSM4(a[mt][0], a[mt][1], a[mt][2], a[mt][3], ad);
            }
#pragma unroll
            for (int n2 = 0; n2 < 2; n2++) {
                const uint32_t bd = (st + offB + n2 * 1024) ^ (uint32_t)(s << 5);
                LDSM4(b[2 * n2][0], b[2 * n2][1], b[2 * n2 + 1][0], b[2 * n2 + 1][1], bd);
            }
#pragma unroll
            for (int mt = 0; mt < 4; mt++)
#pragma unroll
                for (int nt = 0; nt < 4; nt++)
                    IMMA(acc[mt][nt], a[mt], b[nt]);
        }
    }

    // ---- epilogue: acc + czp[m]*rs[n], scale, bias ----
#pragma unroll
    for (int mt = 0; mt < 4; mt++) {
        const int r0 = bm + warp_m + mt * 16 + (lane >> 2);
        const float sa0 = g_sa[r0], cz0 = g_czp[r0];
        const float sa1 = g_sa[r0 + 8], cz1 = g_czp[r0 + 8];
        float* o0 = out + (size_t)r0 * NDIM + bn;
        float* o1 = o0 + (size_t)8 * NDIM;
#pragma unroll
        for (int nt = 0; nt < 4; nt++) {
            const int ncol = warp_n + nt * 8 + ((lane & 3) << 1);
            const int n = bn + ncol;
            const float sw0 = g_sw[n], sw1 = g_sw[n + 1];
            const float rs0 = g_rs[n], rs1 = g_rs[n + 1];
            const float b0 = __ldg(bias + n), b1 = __ldg(bias + n + 1);
            const int* cc = acc[mt][nt];
            float2 y0, y1;
            y0.x = ((float)cc[0] + cz0 * rs0) * (sa0 * sw0) + b0;
            y0.y = ((float)cc[1] + cz0 * rs1) * (sa0 * sw1) + b1;
            y1.x = ((float)cc[2] + cz1 * rs0) * (sa1 * sw0) + b0;
            y1.y = ((float)cc[3] + cz1 * rs1) * (sa1 * sw1) + b1;
            *reinterpret_cast<float2*>(o0 + ncol) = y0;
            *reinterpret_cast<float2*>(o1 + ncol) = y1;
        }
    }
}

// ---------------- host launch ----------------
extern "C" void kernel_launch(void* const* d_in, const int* in_sizes, int n_in,
                              void* d_out, int out_size) {
    (void)in_sizes; (void)n_in; (void)out_size;
    const float* x    = (const float*)d_in[0];
    const float* w    = (const float*)d_in[1];
    const float* bias = (const float*)d_in[2];
    float* out = (float*)d_out;

    quant_x_kernel<<<MDIM, 256>>>(x);
    quant_w_kernel<<<NDIM, 256>>>(w);

    static int smem_set = 0;
    if (!smem_set) {
        cudaFuncSetAttribute(gemm_kernel, cudaFuncAttributeMaxDynamicSharedMemorySize,
                             GEMM_SMEM);
        smem_set = 1;
    }
    gemm_kernel<<<dim3(NDIM / BN, MDIM / BM), 256, GEMM_SMEM>>>(bias, out);
}